// round 14
// baseline (speedup 1.0000x reference)
#include <cuda_runtime.h>
#include <cuda_fp16.h>
#include <cstdint>

// ============================================================================
// out[4096,16384] = f32( fp8( (x_fp8 @ w_fp8^T) / (xs*ws) + bias ) )
// R14: eliminate quant_w — GEMM loads B as raw f32 and converts each thread's
//      own fragment (f32 -> e4m3 grid -> f16) in idle issue slots. Saves the
//      entire quant_w pass (~55us of DRAM time). A path unchanged (f16 staged).
//      3 launches: absmax -> quant_x (relays scales) -> gemm (re-zeros absmax).
// ============================================================================

#define TOKENS   4096
#define NOUT     16384
#define KDIM     4096

#define TM       128
#define TN       128
#define KELEM    64             // K elements per chunk
#define NK_ITERS (KDIM / KELEM) // 64
#define ROWB     (KDIM * 2)     // g_x16 row stride (f16 bytes)
#define WROWB    (KDIM * 4)     // w row stride (f32 bytes)

#define NTHREADS 128
#define A_STAGE  16384          // 128 rows x 128 B (f16)
#define B_STAGE  32768          // 128 rows x 256 B (f32), stored as 2 x 128B halves
#define STAGE_BYTES (A_STAGE + B_STAGE)          // 48 KB
#define SMEM_TOTAL  (2 * STAGE_BYTES)            // 96 KB -> 2 CTAs/SM

#define N4X ((TOKENS * KDIM) / 4)
#define N4W ((NOUT   * KDIM) / 4)

__device__ __align__(128) uint8_t g_x16[(size_t)TOKENS * KDIM * 2];   // 32 MB
__device__ unsigned g_absmax_bits[2];   // zero at load; re-zeroed by gemm tail
__device__ float    g_scales[2];        // relayed by quant_x

// ---------------------------------------------------------------------------
__device__ __forceinline__ uint32_t smem_to_u32(const void* p) {
    uint32_t a;
    asm("{ .reg .u64 t; cvta.to.shared.u64 t, %1; cvt.u32.u64 %0, t; }" : "=r"(a) : "l"(p));
    return a;
}
__device__ __forceinline__ uint16_t cvt2_e4m3(float lo, float hi) {
    uint16_t r;
    asm("cvt.rn.satfinite.e4m3x2.f32 %0, %1, %2;" : "=h"(r) : "f"(hi), "f"(lo));
    return r;
}
__device__ __forceinline__ uint32_t e4m3x2_to_f16x2(uint16_t p) {
    uint32_t h2;
    asm("{ .reg .b16 t; mov.b16 t, %1; cvt.rn.f16x2.e4m3x2 %0, t; }" : "=r"(h2) : "h"(p));
    return h2;
}
__device__ __forceinline__ float2 dec2_e4m3(uint16_t p) {
    uint32_t h2 = e4m3x2_to_f16x2(p);
    __half2 h = *reinterpret_cast<__half2*>(&h2);
    return __half22float2(h);
}
__device__ __forceinline__ void cp_async16(uint32_t smem_dst, const void* gptr) {
    asm volatile("cp.async.cg.shared.global [%0], [%1], 16;" :: "r"(smem_dst), "l"(gptr));
}
__device__ __forceinline__ void cp_commit() {
    asm volatile("cp.async.commit_group;" ::: "memory");
}
template <int N>
__device__ __forceinline__ void cp_wait() {
    asm volatile("cp.async.wait_group %0;" :: "n"(N) : "memory");
}
__device__ __forceinline__ void mma_f16(float* c, const uint32_t* a, const uint32_t* b) {
    asm volatile(
        "mma.sync.aligned.m16n8k16.row.col.f32.f16.f16.f32 "
        "{%0,%1,%2,%3}, {%4,%5,%6,%7}, {%8,%9}, {%0,%1,%2,%3};"
        : "+f"(c[0]), "+f"(c[1]), "+f"(c[2]), "+f"(c[3])
        : "r"(a[0]), "r"(a[1]), "r"(a[2]), "r"(a[3]), "r"(b[0]), "r"(b[1]));
}
__device__ __forceinline__ void ldsm_x4(uint32_t addr,
                                        uint32_t& r0, uint32_t& r1,
                                        uint32_t& r2, uint32_t& r3) {
    asm volatile("ldmatrix.sync.aligned.m8n8.x4.shared.b16 {%0,%1,%2,%3}, [%4];"
                 : "=r"(r0), "=r"(r1), "=r"(r2), "=r"(r3) : "r"(addr));
}
// Swizzle for 128B-wide rows (A tiles and each B half-tile)
__device__ __forceinline__ uint32_t swz(uint32_t row, uint32_t col) {
    return row * 128u + (((col >> 4) ^ (row & 7u)) << 4) + (col & 15u);
}
__device__ __forceinline__ float2 lds_f32x2(uint32_t addr) {
    float2 v;
    asm volatile("ld.shared.v2.f32 {%0, %1}, [%2];" : "=f"(v.x), "=f"(v.y) : "r"(addr));
    return v;
}

// ---------------------------------------------------------------------------
// Launch #1: fused absmax (x and w), front-to-back.
#define AX_XBLK 1536
#define AX_WBLK 4608
__global__ void absmax_fused_kernel(const float4* __restrict__ x,
                                    const float4* __restrict__ w) {
    const int bx = blockIdx.x;
    const bool isX = bx < AX_XBLK;
    const float4* __restrict__ p = isX ? x : w;
    const int n4   = isX ? N4X : N4W;
    const int nblk = isX ? AX_XBLK : AX_WBLK;
    const int bid  = isX ? bx : bx - AX_XBLK;
    const int slot = isX ? 0 : 1;
    const int stride = nblk * blockDim.x;

    float m0 = 0.f, m1 = 0.f;
    for (int i = bid * blockDim.x + threadIdx.x; i < n4; i += 2 * stride) {
        float4 v = p[i];
        const int j = i + stride;
        if (j < n4) {
            float4 u = p[j];
            m1 = fmaxf(m1, fmaxf(fmaxf(fabsf(u.x), fabsf(u.y)),
                                 fmaxf(fabsf(u.z), fabsf(u.w))));
        }
        m0 = fmaxf(m0, fmaxf(fmaxf(fabsf(v.x), fabsf(v.y)),
                             fmaxf(fabsf(v.z), fabsf(v.w))));
    }
    float m = fmaxf(m0, m1);
    #pragma unroll
    for (int o = 16; o; o >>= 1) m = fmaxf(m, __shfl_xor_sync(0xffffffffu, m, o));
    __shared__ float sm[32];
    if ((threadIdx.x & 31) == 0) sm[threadIdx.x >> 5] = m;
    __syncthreads();
    if (threadIdx.x < 32) {
        float v = (threadIdx.x < (blockDim.x >> 5)) ? sm[threadIdx.x] : 0.f;
        #pragma unroll
        for (int o = 16; o; o >>= 1) v = fmaxf(v, __shfl_xor_sync(0xffffffffu, v, o));
        if (threadIdx.x == 0) atomicMax(&g_absmax_bits[slot], __float_as_uint(v));
    }
}

// Launch #2: quantize x -> f16 on e4m3 grid; block 0 relays both scales.
__global__ void quant_x_kernel(const float4* __restrict__ x) {
    if (blockIdx.x == 0 && threadIdx.x < 2)
        g_scales[threadIdx.x] = __uint_as_float(g_absmax_bits[threadIdx.x]);
    uint4* __restrict__ out = (uint4*)g_x16;
    const int n8 = N4X / 2;
    float amax = __uint_as_float(g_absmax_bits[0]);
    float s = 448.f / (amax + 1e-6f);
    for (int i = blockIdx.x * blockDim.x + threadIdx.x; i < n8;
         i += gridDim.x * blockDim.x) {
        float4 a = x[2 * i];
        float4 b = x[2 * i + 1];
        uint4 o;
        o.x = e4m3x2_to_f16x2(cvt2_e4m3(a.x * s, a.y * s));
        o.y = e4m3x2_to_f16x2(cvt2_e4m3(a.z * s, a.w * s));
        o.z = e4m3x2_to_f16x2(cvt2_e4m3(b.x * s, b.y * s));
        o.w = e4m3x2_to_f16x2(cvt2_e4m3(b.z * s, b.w * s));
        out[i] = o;
    }
}

// ---------------------------------------------------------------------------
// Launch #3: GEMM. A staged f16 (ldmatrix); B staged RAW F32, converted
// per-thread to its own mma fragment (f32 -> e4m3 grid -> f16). 2-stage
// cp.async pipeline, 1 barrier per k-iter, occ 2.
// ---------------------------------------------------------------------------
__global__ __launch_bounds__(NTHREADS, 2)
void gemm_kernel(const float* __restrict__ w, const float* __restrict__ bias,
                 float* __restrict__ out)
{
    extern __shared__ char smem[];
    const uint32_t smem_u32 = smem_to_u32(smem);

    const int tid  = threadIdx.x;
    const int wid  = tid >> 5;
    const int lid  = tid & 31;
    const int lr   = lid >> 2;
    const int lc   = lid & 3;
    const int warpM = wid & 1;
    const int warpN = wid >> 1;
    const int lt   = lid & 7;
    const int tile = lid >> 3;

    const unsigned mBase = blockIdx.x * TM;
    const unsigned nBase = blockIdx.y * TN;

    const float sx = 448.f / (g_scales[0] + 1e-6f);
    const float sw = 448.f / (g_scales[1] + 1e-6f);
    const float inv = 1.0f / (sx * sw);

    const uint8_t* __restrict__ gA = g_x16 + (size_t)mBase * ROWB;
    const uint8_t* __restrict__ gB = (const uint8_t*)w + (size_t)nBase * WROWB;

    // stage layout: [A f16 16KB][B f32 32KB = half0 16KB | half1 16KB]
    auto load_stage = [&](int st, int kc) {
        const uint32_t sa = smem_u32 + st * STAGE_BYTES;
        const uint32_t sb = sa + A_STAGE;
        const unsigned kOffA = (unsigned)kc * 128u;   // f16 bytes
        const unsigned kOffB = (unsigned)kc * 256u;   // f32 bytes
        #pragma unroll
        for (int t = 0; t < 8; t++) {                 // A: 1024 granules
            unsigned idx = tid + t * NTHREADS;
            unsigned row = idx >> 3, g = (idx & 7) << 4;
            cp_async16(sa + swz(row, g), gA + (size_t)row * ROWB + kOffA + g);
        }
        #pragma unroll
        for (int t = 0; t < 16; t++) {                // B: 2048 granules (f32)
            unsigned idx = tid + t * NTHREADS;
            unsigned row = idx >> 4, g = (idx & 15) << 4;   // g: 0..240 bytes
            cp_async16(sb + (g >= 128u ? 16384u : 0u) + swz(row, g & 127u),
                       gB + (size_t)row * WROWB + kOffB + g);
        }
    };

    float acc[4][8][4];
    #pragma unroll
    for (int mi = 0; mi < 4; mi++)
        #pragma unroll
        for (int ni = 0; ni < 8; ni++)
            #pragma unroll
            for (int q = 0; q < 4; q++) acc[mi][ni][q] = 0.f;

    const unsigned aRow     = (unsigned)(warpM * 64 + (tile & 1) * 8 + lt);
    const unsigned aColHalf = (unsigned)((tile >> 1) * 16);
    const unsigned bRowBase = (unsigned)(warpN * 64 + lr);   // + ni*8

    load_stage(0, 0); cp_commit();

    for (int kc = 0; kc < NK_ITERS; kc++) {
        cp_wait<0>();
        __syncthreads();   // stage kc ready; all compute(kc-1) finished

        if (kc + 1 < NK_ITERS) {               // prefetch into other buffer
            load_stage((kc + 1) & 1, kc + 1);  // safe: buf computed at kc-1
            cp_commit();
        }

        const int st = kc & 1;
        const uint32_t sa = smem_u32 + st * STAGE_BYTES;
        const uint32_t sb = sa + A_STAGE;

        #pragma unroll
        for (int ks = 0; ks < 4; ks++) {
            const unsigned cb = (unsigned)ks * 32u;        // f16-byte base (A)
            uint32_t af[4][4];
            #pragma unroll
            for (int mi = 0; mi < 4; mi++)
                ldsm_x4(sa + swz(aRow + mi * 16u, cb + aColHalf),
                        af[mi][0], af[mi][1], af[mi][2], af[mi][3]);
            // B fragments direct from f32 tile:
            // bf[ni][q] = f16x2{ B[n][k], B[n][k+1] }, n = bRowBase+ni*8,
            // k = ks*16 + q*8 + lc*2  (f32 byte = k*4; half = byte>=128)
            uint32_t bf[8][2];
            #pragma unroll
            for (int ni = 0; ni < 8; ni++) {
                const unsigned n = bRowBase + ni * 8u;
                #pragma unroll
                for (int q = 0; q < 2; q++) {
                    const unsigned kb = (ks * 16u + q * 8u + lc * 2u) * 4u;
                    const uint32_t addr = sb + (kb >= 128u ? 16384u : 0u)
                                        + swz(n, kb & 127u);
                    float2 v = lds_f32x2(addr);
                    bf[ni][q] = e4m3x2_to_f16x2(cvt2_e4m3(v.x * sw, v.y * sw));
                }
            }
            #pragma unroll
            for (int mi = 0; mi < 4; mi++)
                #pragma unroll
                for (int ni = 0; ni < 8; ni++)
                    mma_f16(acc[mi][ni], af[mi], bf[ni]);
        }
    }

    // epilogue: descale + bias -> fp8 round -> decode -> f32 store
    #pragma unroll
    for (int mi = 0; mi < 4; mi++) {
        const unsigned r0 = mBase + warpM * 64 + mi * 16 + lr;
        #pragma unroll
        for (int ni = 0; ni < 8; ni++) {
            const unsigned c = nBase + warpN * 64 + ni * 8 + lc * 2;
            const float2 bv = *(const float2*)(bias + c);
            const float* a = acc[mi][ni];
            uint16_t p0 = cvt2_e4m3(fmaf(a[0], inv, bv.x), fmaf(a[1], inv, bv.y));
            uint16_t p1 = cvt2_e4m3(fmaf(a[2], inv, bv.x), fmaf(a[3], inv, bv.y));
            float2 f0 = dec2_e4m3(p0);
            float2 f1 = dec2_e4m3(p1);
            *(float2*)(out + (size_t)r0       * NOUT + c) = f0;
            *(float2*)(out + (size_t)(r0 + 8) * NOUT + c) = f1;
        }
    }

    // re-zero absmax accumulators for the next replay (no reader in this
    // kernel — all blocks read g_scales; idempotent stores, deterministic)
    if (tid < 2) g_absmax_bits[tid] = 0u;
}

// ---------------------------------------------------------------------------
extern "C" void kernel_launch(void* const* d_in, const int* in_sizes, int n_in,
                              void* d_out, int out_size)
{
    const float* x = (const float*)d_in[0];
    const float* w = (const float*)d_in[1];
    const float* b = (const float*)d_in[2];
    float* out = (float*)d_out;

    absmax_fused_kernel<<<AX_XBLK + AX_WBLK, 256>>>((const float4*)x,
                                                    (const float4*)w);   // #1
    quant_x_kernel<<<2048, 256>>>((const float4*)x);                     // #2

    cudaFuncSetAttribute(gemm_kernel, cudaFuncAttributeMaxDynamicSharedMemorySize, SMEM_TOTAL);
    dim3 grid(TOKENS / TM, NOUT / TN);   // (32, 128)
    gemm_kernel<<<grid, NTHREADS, SMEM_TOTAL>>>(w, b, out);              // #3

    (void)in_sizes; (void)n_in; (void)out_size;
}

// round 15
// speedup vs baseline: 1.2379x; 1.2379x over previous
#include <cuda_runtime.h>
#include <cuda_fp16.h>
#include <cstdint>

// ============================================================================
// out[4096,16384] = f32( fp8( (x_fp8 @ w_fp8^T) / (xs*ws) + bias ) )
// R15: best-known GEMM (R10, tensor-pipe ceiling) + prepass slack removal:
//      - init_kernel deleted (gemm tail re-zeros absmax; quant relays scales)
//      - quant restructured for MLP=4 (2 independent uint4 streams/thread)
// ============================================================================

#define TOKENS   4096
#define NOUT     16384
#define KDIM     4096

#define TM       128
#define TN       128
#define TKB      128            // K-chunk bytes per smem row = 64 f16
#define KELEM    64
#define STAGES   3
#define NK_ITERS (KDIM / KELEM) // 64
#define ROWB     (KDIM * 2)

#define NTHREADS 128
#define STAGE_BYTES 16384
#define SMEM_TOTAL  (STAGES * 2 * STAGE_BYTES)   // 96 KB -> 2 CTAs/SM

#define N4X ((TOKENS * KDIM) / 4)
#define N4W ((NOUT   * KDIM) / 4)

__device__ __align__(128) uint8_t g_x16[(size_t)TOKENS * KDIM * 2];   // 32 MB
__device__ __align__(128) uint8_t g_w16[(size_t)NOUT   * KDIM * 2];   // 128 MB
__device__ unsigned g_absmax_bits[2];   // zeroed at load; re-zeroed by gemm tail
__device__ float    g_scales[2];        // relayed by quant (amax values)

// ---------------------------------------------------------------------------
__device__ __forceinline__ uint32_t smem_to_u32(const void* p) {
    uint32_t a;
    asm("{ .reg .u64 t; cvta.to.shared.u64 t, %1; cvt.u32.u64 %0, t; }" : "=r"(a) : "l"(p));
    return a;
}
__device__ __forceinline__ uint16_t cvt2_e4m3(float lo, float hi) {
    uint16_t r;
    asm("cvt.rn.satfinite.e4m3x2.f32 %0, %1, %2;" : "=h"(r) : "f"(hi), "f"(lo));
    return r;
}
__device__ __forceinline__ uint32_t e4m3x2_to_f16x2(uint16_t p) {
    uint32_t h2;
    asm("{ .reg .b16 t; mov.b16 t, %1; cvt.rn.f16x2.e4m3x2 %0, t; }" : "=r"(h2) : "h"(p));
    return h2;
}
__device__ __forceinline__ float2 dec2_e4m3(uint16_t p) {
    uint32_t h2 = e4m3x2_to_f16x2(p);
    __half2 h = *reinterpret_cast<__half2*>(&h2);
    return __half22float2(h);
}
__device__ __forceinline__ void cp_async16(uint32_t smem_dst, const void* gptr) {
    asm volatile("cp.async.cg.shared.global [%0], [%1], 16;" :: "r"(smem_dst), "l"(gptr));
}
__device__ __forceinline__ void cp_commit() {
    asm volatile("cp.async.commit_group;" ::: "memory");
}
template <int N>
__device__ __forceinline__ void cp_wait() {
    asm volatile("cp.async.wait_group %0;" :: "n"(N) : "memory");
}
__device__ __forceinline__ void mma_f16(float* c, const uint32_t* a, const uint32_t* b) {
    asm volatile(
        "mma.sync.aligned.m16n8k16.row.col.f32.f16.f16.f32 "
        "{%0,%1,%2,%3}, {%4,%5,%6,%7}, {%8,%9}, {%0,%1,%2,%3};"
        : "+f"(c[0]), "+f"(c[1]), "+f"(c[2]), "+f"(c[3])
        : "r"(a[0]), "r"(a[1]), "r"(a[2]), "r"(a[3]), "r"(b[0]), "r"(b[1]));
}
__device__ __forceinline__ void ldsm_x4(uint32_t addr,
                                        uint32_t& r0, uint32_t& r1,
                                        uint32_t& r2, uint32_t& r3) {
    asm volatile("ldmatrix.sync.aligned.m8n8.x4.shared.b16 {%0,%1,%2,%3}, [%4];"
                 : "=r"(r0), "=r"(r1), "=r"(r2), "=r"(r3) : "r"(addr));
}
__device__ __forceinline__ uint32_t swz(uint32_t row, uint32_t col) {
    return row * 128u + (((col >> 4) ^ (row & 7u)) << 4) + (col & 15u);
}

// ---------------------------------------------------------------------------
// Launch #1: fused absmax (81% DRAM measured — keep structure)
#define AX_XBLK 1536
#define AX_WBLK 4608
__global__ void absmax_fused_kernel(const float4* __restrict__ x,
                                    const float4* __restrict__ w) {
    const int bx = blockIdx.x;
    const bool isX = bx < AX_XBLK;
    const float4* __restrict__ p = isX ? x : w;
    const int n4   = isX ? N4X : N4W;
    const int nblk = isX ? AX_XBLK : AX_WBLK;
    const int bid  = isX ? bx : bx - AX_XBLK;
    const int slot = isX ? 0 : 1;
    const int stride = nblk * blockDim.x;

    float m0 = 0.f, m1 = 0.f;
    for (int i = bid * blockDim.x + threadIdx.x; i < n4; i += 2 * stride) {
        float4 v = p[i];
        const int j = i + stride;
        if (j < n4) {
            float4 u = p[j];
            m1 = fmaxf(m1, fmaxf(fmaxf(fabsf(u.x), fabsf(u.y)),
                                 fmaxf(fabsf(u.z), fabsf(u.w))));
        }
        m0 = fmaxf(m0, fmaxf(fmaxf(fabsf(v.x), fabsf(v.y)),
                             fmaxf(fabsf(v.z), fabsf(v.w))));
    }
    float m = fmaxf(m0, m1);
    #pragma unroll
    for (int o = 16; o; o >>= 1) m = fmaxf(m, __shfl_xor_sync(0xffffffffu, m, o));
    __shared__ float sm[32];
    if ((threadIdx.x & 31) == 0) sm[threadIdx.x >> 5] = m;
    __syncthreads();
    if (threadIdx.x < 32) {
        float v = (threadIdx.x < (blockDim.x >> 5)) ? sm[threadIdx.x] : 0.f;
        #pragma unroll
        for (int o = 16; o; o >>= 1) v = fmaxf(v, __shfl_xor_sync(0xffffffffu, v, o));
        if (threadIdx.x == 0) atomicMax(&g_absmax_bits[slot], __float_as_uint(v));
    }
}

// ---------------------------------------------------------------------------
// Launch #2: fused quant, MLP=4 (two independent 32B input streams/thread).
// Block 0 relays absmax values into g_scales for the GEMM.
#define QT_XBLK 2048
#define QT_WBLK 6144
__global__ void quant_fused_kernel(const float4* __restrict__ x,
                                   const float4* __restrict__ w) {
    if (blockIdx.x == 0 && threadIdx.x < 2)
        g_scales[threadIdx.x] = __uint_as_float(g_absmax_bits[threadIdx.x]);

    const int bx = blockIdx.x;
    const bool isX = bx < QT_XBLK;
    const float4* __restrict__ in = isX ? x : w;
    uint4* __restrict__ out = isX ? (uint4*)g_x16 : (uint4*)g_w16;
    const int n8   = (isX ? N4X : N4W) / 2;
    const int nblk = isX ? QT_XBLK : QT_WBLK;
    const int bid  = isX ? bx : bx - QT_XBLK;
    const int stride = nblk * blockDim.x;

    float amax = __uint_as_float(g_absmax_bits[isX ? 0 : 1]);
    float s = 448.f / (amax + 1e-6f);

    for (int i = bid * blockDim.x + threadIdx.x; i < n8; i += 2 * stride) {
        const int j = i + stride;
        // issue all 4 independent float4 loads first (MLP=4)
        float4 a0 = in[2 * i];
        float4 a1 = in[2 * i + 1];
        float4 b0, b1;
        if (j < n8) { b0 = in[2 * j]; b1 = in[2 * j + 1]; }
        uint4 o0;
        o0.x = e4m3x2_to_f16x2(cvt2_e4m3(a0.x * s, a0.y * s));
        o0.y = e4m3x2_to_f16x2(cvt2_e4m3(a0.z * s, a0.w * s));
        o0.z = e4m3x2_to_f16x2(cvt2_e4m3(a1.x * s, a1.y * s));
        o0.w = e4m3x2_to_f16x2(cvt2_e4m3(a1.z * s, a1.w * s));
        out[i] = o0;
        if (j < n8) {
            uint4 o1;
            o1.x = e4m3x2_to_f16x2(cvt2_e4m3(b0.x * s, b0.y * s));
            o1.y = e4m3x2_to_f16x2(cvt2_e4m3(b0.z * s, b0.w * s));
            o1.z = e4m3x2_to_f16x2(cvt2_e4m3(b1.x * s, b1.y * s));
            o1.w = e4m3x2_to_f16x2(cvt2_e4m3(b1.z * s, b1.w * s));
            out[j] = o1;
        }
    }
}

// ---------------------------------------------------------------------------
// Launch #3: GEMM — IDENTICAL inner loop to R10 best (tensor-pipe ceiling).
// CTA 128x128, 4 warps, warp tile 64x64, 3-stage cp.async, occ 2.
// Reads g_scales (relayed); re-zeros g_absmax_bits at tail (no reader here).
// ---------------------------------------------------------------------------
__global__ __launch_bounds__(NTHREADS, 2)
void gemm_kernel(const float* __restrict__ bias, float* __restrict__ out)
{
    extern __shared__ char smem[];
    const uint32_t smem_u32 = smem_to_u32(smem);

    const int tid  = threadIdx.x;
    const int wid  = tid >> 5;
    const int lid  = tid & 31;
    const int lr   = lid >> 2;
    const int lc   = lid & 3;
    const int warpM = wid & 1;
    const int warpN = wid >> 1;
    const int lt   = lid & 7;
    const int tile = lid >> 3;

    const unsigned mBase = blockIdx.x * TM;
    const unsigned nBase = blockIdx.y * TN;

    const uint8_t* __restrict__ gA = g_x16 + (size_t)mBase * ROWB;
    const uint8_t* __restrict__ gB = g_w16 + (size_t)nBase * ROWB;

    auto load_stage = [&](int st, int kc) {
        const unsigned kOff = (unsigned)kc * TKB;
        const uint32_t sa = smem_u32 + st * 2 * STAGE_BYTES;
        const uint32_t sb = sa + STAGE_BYTES;
        #pragma unroll
        for (int t = 0; t < 8; t++) {
            unsigned idx = tid + t * NTHREADS;
            unsigned row = idx >> 3, g = (idx & 7) << 4;
            cp_async16(sa + swz(row, g), gA + (size_t)row * ROWB + kOff + g);
        }
        #pragma unroll
        for (int t = 0; t < 8; t++) {
            unsigned idx = tid + t * NTHREADS;
            unsigned row = idx >> 3, g = (idx & 7) << 4;
            cp_async16(sb + swz(row, g), gB + (size_t)row * ROWB + kOff + g);
        }
    };

    float acc[4][8][4];
    #pragma unroll
    for (int mi = 0; mi < 4; mi++)
        #pragma unroll
        for (int ni = 0; ni < 8; ni++)
            #pragma unroll
            for (int q = 0; q < 4; q++) acc[mi][ni][q] = 0.f;

    const unsigned aRow     = (unsigned)(warpM * 64 + (tile & 1) * 8 + lt);
    const unsigned aColHalf = (unsigned)((tile >> 1) * 16);
    const unsigned bRow     = (unsigned)(warpN * 64 + (tile >> 1) * 8 + lt);
    const unsigned bColHalf = (unsigned)((tile & 1) * 16);

    load_stage(0, 0); cp_commit();
    load_stage(1, 1); cp_commit();

    for (int kc = 0; kc < NK_ITERS; kc++) {
        cp_wait<STAGES - 2>();
        __syncthreads();

        if (kc + STAGES - 1 < NK_ITERS) {
            load_stage((kc + STAGES - 1) % STAGES, kc + STAGES - 1);
            cp_commit();
        }

        const int st = kc % STAGES;
        const uint32_t sa = smem_u32 + st * 2 * STAGE_BYTES;
        const uint32_t sb = sa + STAGE_BYTES;

        #pragma unroll
        for (int ks = 0; ks < 4; ks++) {
            const unsigned cb = (unsigned)ks * 32u;
            uint32_t af[4][4];
            #pragma unroll
            for (int mi = 0; mi < 4; mi++)
                ldsm_x4(sa + swz(aRow + mi * 16u, cb + aColHalf),
                        af[mi][0], af[mi][1], af[mi][2], af[mi][3]);
            uint32_t bf[8][2];
            #pragma unroll
            for (int p = 0; p < 4; p++)
                ldsm_x4(sb + swz(bRow + p * 16u, cb + bColHalf),
                        bf[2*p][0], bf[2*p][1], bf[2*p+1][0], bf[2*p+1][1]);
            #pragma unroll
            for (int mi = 0; mi < 4; mi++)
                #pragma unroll
                for (int ni = 0; ni < 8; ni++)
                    mma_f16(acc[mi][ni], af[mi], bf[ni]);
        }
    }

    const float sx = 448.f / (g_scales[0] + 1e-6f);
    const float sw = 448.f / (g_scales[1] + 1e-6f);
    const float inv = 1.0f / (sx * sw);

    #pragma unroll
    for (int mi = 0; mi < 4; mi++) {
        const unsigned r0 = mBase + warpM * 64 + mi * 16 + lr;
        #pragma unroll
        for (int ni = 0; ni < 8; ni++) {
            const unsigned c = nBase + warpN * 64 + ni * 8 + lc * 2;
            const float2 bv = *(const float2*)(bias + c);
            const float* a = acc[mi][ni];
            uint16_t p0 = cvt2_e4m3(fmaf(a[0], inv, bv.x), fmaf(a[1], inv, bv.y));
            uint16_t p1 = cvt2_e4m3(fmaf(a[2], inv, bv.x), fmaf(a[3], inv, bv.y));
            float2 f0 = dec2_e4m3(p0);
            float2 f1 = dec2_e4m3(p1);
            *(float2*)(out + (size_t)r0       * NOUT + c) = f0;
            *(float2*)(out + (size_t)(r0 + 8) * NOUT + c) = f1;
        }
    }

    // Re-zero absmax accumulators for the next graph replay. No kernel after
    // this point reads g_absmax_bits (GEMM uses g_scales), so no race;
    // idempotent stores keep replays deterministic.
    if (tid < 2) g_absmax_bits[tid] = 0u;
}

// ---------------------------------------------------------------------------
extern "C" void kernel_launch(void* const* d_in, const int* in_sizes, int n_in,
                              void* d_out, int out_size)
{
    const float* x = (const float*)d_in[0];
    const float* w = (const float*)d_in[1];
    const float* b = (const float*)d_in[2];
    float* out = (float*)d_out;

    absmax_fused_kernel<<<AX_XBLK + AX_WBLK, 256>>>((const float4*)x,
                                                    (const float4*)w);   // #1
    quant_fused_kernel<<<QT_XBLK + QT_WBLK, 256>>>((const float4*)x,
                                                   (const float4*)w);    // #2

    cudaFuncSetAttribute(gemm_kernel, cudaFuncAttributeMaxDynamicSharedMemorySize, SMEM_TOTAL);
    dim3 grid(TOKENS / TM, NOUT / TN);   // (32, 128)
    gemm_kernel<<<grid, NTHREADS, SMEM_TOTAL>>>(b, out);                 // #3

    (void)in_sizes; (void)n_in; (void)out_size;
}

// round 16
// speedup vs baseline: 1.3318x; 1.0758x over previous
#include <cuda_runtime.h>
#include <cuda_fp16.h>
#include <cstdint>

// ============================================================================
// out[4096,16384] = f32( fp8( (x_fp8 @ w_fp8^T) / (xs*ws) + bias ) )
// R16: attack the ~512cyc/iter GEMM boundary bubble. The asm-volatile cp.async
//      batch (16 ops + ~60 addr instrs) was pinned BEFORE the first LDSM each
//      iter, delaying the critical fragment chain. Reorder: barrier -> ks=0
//      LDSMs -> cp.async issue -> MMAs. Prepass identical to R15.
// ============================================================================

#define TOKENS   4096
#define NOUT     16384
#define KDIM     4096

#define TM       128
#define TN       128
#define TKB      128            // K-chunk bytes per smem row = 64 f16
#define KELEM    64
#define STAGES   3
#define NK_ITERS (KDIM / KELEM) // 64
#define ROWB     (KDIM * 2)

#define NTHREADS 128
#define STAGE_BYTES 16384
#define SMEM_TOTAL  (STAGES * 2 * STAGE_BYTES)   // 96 KB -> 2 CTAs/SM

#define N4X ((TOKENS * KDIM) / 4)
#define N4W ((NOUT   * KDIM) / 4)

__device__ __align__(128) uint8_t g_x16[(size_t)TOKENS * KDIM * 2];   // 32 MB
__device__ __align__(128) uint8_t g_w16[(size_t)NOUT   * KDIM * 2];   // 128 MB
__device__ unsigned g_absmax_bits[2];   // zeroed at load; re-zeroed by gemm tail
__device__ float    g_scales[2];        // relayed by quant (amax values)

// ---------------------------------------------------------------------------
__device__ __forceinline__ uint32_t smem_to_u32(const void* p) {
    uint32_t a;
    asm("{ .reg .u64 t; cvta.to.shared.u64 t, %1; cvt.u32.u64 %0, t; }" : "=r"(a) : "l"(p));
    return a;
}
__device__ __forceinline__ uint16_t cvt2_e4m3(float lo, float hi) {
    uint16_t r;
    asm("cvt.rn.satfinite.e4m3x2.f32 %0, %1, %2;" : "=h"(r) : "f"(hi), "f"(lo));
    return r;
}
__device__ __forceinline__ uint32_t e4m3x2_to_f16x2(uint16_t p) {
    uint32_t h2;
    asm("{ .reg .b16 t; mov.b16 t, %1; cvt.rn.f16x2.e4m3x2 %0, t; }" : "=r"(h2) : "h"(p));
    return h2;
}
__device__ __forceinline__ float2 dec2_e4m3(uint16_t p) {
    uint32_t h2 = e4m3x2_to_f16x2(p);
    __half2 h = *reinterpret_cast<__half2*>(&h2);
    return __half22float2(h);
}
__device__ __forceinline__ void cp_async16(uint32_t smem_dst, const void* gptr) {
    asm volatile("cp.async.cg.shared.global [%0], [%1], 16;" :: "r"(smem_dst), "l"(gptr));
}
__device__ __forceinline__ void cp_commit() {
    asm volatile("cp.async.commit_group;" ::: "memory");
}
template <int N>
__device__ __forceinline__ void cp_wait() {
    asm volatile("cp.async.wait_group %0;" :: "n"(N) : "memory");
}
__device__ __forceinline__ void mma_f16(float* c, const uint32_t* a, const uint32_t* b) {
    asm volatile(
        "mma.sync.aligned.m16n8k16.row.col.f32.f16.f16.f32 "
        "{%0,%1,%2,%3}, {%4,%5,%6,%7}, {%8,%9}, {%0,%1,%2,%3};"
        : "+f"(c[0]), "+f"(c[1]), "+f"(c[2]), "+f"(c[3])
        : "r"(a[0]), "r"(a[1]), "r"(a[2]), "r"(a[3]), "r"(b[0]), "r"(b[1]));
}
__device__ __forceinline__ void ldsm_x4(uint32_t addr,
                                        uint32_t& r0, uint32_t& r1,
                                        uint32_t& r2, uint32_t& r3) {
    asm volatile("ldmatrix.sync.aligned.m8n8.x4.shared.b16 {%0,%1,%2,%3}, [%4];"
                 : "=r"(r0), "=r"(r1), "=r"(r2), "=r"(r3) : "r"(addr));
}
__device__ __forceinline__ uint32_t swz(uint32_t row, uint32_t col) {
    return row * 128u + (((col >> 4) ^ (row & 7u)) << 4) + (col & 15u);
}

// ---------------------------------------------------------------------------
// Launch #1: fused absmax (83% DRAM measured — at floor, keep)
#define AX_XBLK 1536
#define AX_WBLK 4608
__global__ void absmax_fused_kernel(const float4* __restrict__ x,
                                    const float4* __restrict__ w) {
    const int bx = blockIdx.x;
    const bool isX = bx < AX_XBLK;
    const float4* __restrict__ p = isX ? x : w;
    const int n4   = isX ? N4X : N4W;
    const int nblk = isX ? AX_XBLK : AX_WBLK;
    const int bid  = isX ? bx : bx - AX_XBLK;
    const int slot = isX ? 0 : 1;
    const int stride = nblk * blockDim.x;

    float m0 = 0.f, m1 = 0.f;
    for (int i = bid * blockDim.x + threadIdx.x; i < n4; i += 2 * stride) {
        float4 v = p[i];
        const int j = i + stride;
        if (j < n4) {
            float4 u = p[j];
            m1 = fmaxf(m1, fmaxf(fmaxf(fabsf(u.x), fabsf(u.y)),
                                 fmaxf(fabsf(u.z), fabsf(u.w))));
        }
        m0 = fmaxf(m0, fmaxf(fmaxf(fabsf(v.x), fabsf(v.y)),
                             fmaxf(fabsf(v.z), fabsf(v.w))));
    }
    float m = fmaxf(m0, m1);
    #pragma unroll
    for (int o = 16; o; o >>= 1) m = fmaxf(m, __shfl_xor_sync(0xffffffffu, m, o));
    __shared__ float sm[32];
    if ((threadIdx.x & 31) == 0) sm[threadIdx.x >> 5] = m;
    __syncthreads();
    if (threadIdx.x < 32) {
        float v = (threadIdx.x < (blockDim.x >> 5)) ? sm[threadIdx.x] : 0.f;
        #pragma unroll
        for (int o = 16; o; o >>= 1) v = fmaxf(v, __shfl_xor_sync(0xffffffffu, v, o));
        if (threadIdx.x == 0) atomicMax(&g_absmax_bits[slot], __float_as_uint(v));
    }
}

// ---------------------------------------------------------------------------
// Launch #2: fused quant (identical to R15); block 0 relays scales.
#define QT_XBLK 2048
#define QT_WBLK 6144
__global__ void quant_fused_kernel(const float4* __restrict__ x,
                                   const float4* __restrict__ w) {
    if (blockIdx.x == 0 && threadIdx.x < 2)
        g_scales[threadIdx.x] = __uint_as_float(g_absmax_bits[threadIdx.x]);

    const int bx = blockIdx.x;
    const bool isX = bx < QT_XBLK;
    const float4* __restrict__ in = isX ? x : w;
    uint4* __restrict__ out = isX ? (uint4*)g_x16 : (uint4*)g_w16;
    const int n8   = (isX ? N4X : N4W) / 2;
    const int nblk = isX ? QT_XBLK : QT_WBLK;
    const int bid  = isX ? bx : bx - QT_XBLK;
    const int stride = nblk * blockDim.x;

    float amax = __uint_as_float(g_absmax_bits[isX ? 0 : 1]);
    float s = 448.f / (amax + 1e-6f);

    for (int i = bid * blockDim.x + threadIdx.x; i < n8; i += 2 * stride) {
        const int j = i + stride;
        float4 a0 = in[2 * i];
        float4 a1 = in[2 * i + 1];
        float4 b0, b1;
        if (j < n8) { b0 = in[2 * j]; b1 = in[2 * j + 1]; }
        uint4 o0;
        o0.x = e4m3x2_to_f16x2(cvt2_e4m3(a0.x * s, a0.y * s));
        o0.y = e4m3x2_to_f16x2(cvt2_e4m3(a0.z * s, a0.w * s));
        o0.z = e4m3x2_to_f16x2(cvt2_e4m3(a1.x * s, a1.y * s));
        o0.w = e4m3x2_to_f16x2(cvt2_e4m3(a1.z * s, a1.w * s));
        out[i] = o0;
        if (j < n8) {
            uint4 o1;
            o1.x = e4m3x2_to_f16x2(cvt2_e4m3(b0.x * s, b0.y * s));
            o1.y = e4m3x2_to_f16x2(cvt2_e4m3(b0.z * s, b0.w * s));
            o1.z = e4m3x2_to_f16x2(cvt2_e4m3(b1.x * s, b1.y * s));
            o1.w = e4m3x2_to_f16x2(cvt2_e4m3(b1.z * s, b1.w * s));
            out[j] = o1;
        }
    }
}

// ---------------------------------------------------------------------------
// Launch #3: GEMM. Same tiles/pipeline as R10/R15, but the inner-loop body
// is reordered: barrier -> ks=0 LDSMs (critical path) -> cp.async issue ->
// ks=0 MMAs -> ks=1..3. asm-volatile order pins SASS order, so this is real.
// ---------------------------------------------------------------------------
__global__ __launch_bounds__(NTHREADS, 2)
void gemm_kernel(const float* __restrict__ bias, float* __restrict__ out)
{
    extern __shared__ char smem[];
    const uint32_t smem_u32 = smem_to_u32(smem);

    const int tid  = threadIdx.x;
    const int wid  = tid >> 5;
    const int lid  = tid & 31;
    const int lr   = lid >> 2;
    const int lc   = lid & 3;
    const int warpM = wid & 1;
    const int warpN = wid >> 1;
    const int lt   = lid & 7;
    const int tile = lid >> 3;

    const unsigned mBase = blockIdx.x * TM;
    const unsigned nBase = blockIdx.y * TN;

    const uint8_t* __restrict__ gA = g_x16 + (size_t)mBase * ROWB;
    const uint8_t* __restrict__ gB = g_w16 + (size_t)nBase * ROWB;

    auto load_stage = [&](int st, int kc) {
        const unsigned kOff = (unsigned)kc * TKB;
        const uint32_t sa = smem_u32 + st * 2 * STAGE_BYTES;
        const uint32_t sb = sa + STAGE_BYTES;
        #pragma unroll
        for (int t = 0; t < 8; t++) {
            unsigned idx = tid + t * NTHREADS;
            unsigned row = idx >> 3, g = (idx & 7) << 4;
            cp_async16(sa + swz(row, g), gA + (size_t)row * ROWB + kOff + g);
        }
        #pragma unroll
        for (int t = 0; t < 8; t++) {
            unsigned idx = tid + t * NTHREADS;
            unsigned row = idx >> 3, g = (idx & 7) << 4;
            cp_async16(sb + swz(row, g), gB + (size_t)row * ROWB + kOff + g);
        }
    };

    float acc[4][8][4];
    #pragma unroll
    for (int mi = 0; mi < 4; mi++)
        #pragma unroll
        for (int ni = 0; ni < 8; ni++)
            #pragma unroll
            for (int q = 0; q < 4; q++) acc[mi][ni][q] = 0.f;

    const unsigned aRow     = (unsigned)(warpM * 64 + (tile & 1) * 8 + lt);
    const unsigned aColHalf = (unsigned)((tile >> 1) * 16);
    const unsigned bRow     = (unsigned)(warpN * 64 + (tile >> 1) * 8 + lt);
    const unsigned bColHalf = (unsigned)((tile & 1) * 16);

    load_stage(0, 0); cp_commit();
    load_stage(1, 1); cp_commit();

    for (int kc = 0; kc < NK_ITERS; kc++) {
        cp_wait<STAGES - 2>();
        __syncthreads();

        const int st = kc % STAGES;
        const uint32_t sa = smem_u32 + st * 2 * STAGE_BYTES;
        const uint32_t sb = sa + STAGE_BYTES;

        // --- critical path first: ks=0 fragments ---
        uint32_t af0[4][4];
        #pragma unroll
        for (int mi = 0; mi < 4; mi++)
            ldsm_x4(sa + swz(aRow + mi * 16u, aColHalf),
                    af0[mi][0], af0[mi][1], af0[mi][2], af0[mi][3]);
        uint32_t bf0[8][2];
        #pragma unroll
        for (int p = 0; p < 4; p++)
            ldsm_x4(sb + swz(bRow + p * 16u, bColHalf),
                    bf0[2*p][0], bf0[2*p][1], bf0[2*p+1][0], bf0[2*p+1][1]);

        // --- next stage's global loads (2-iter slack; off critical path) ---
        if (kc + STAGES - 1 < NK_ITERS) {
            load_stage((kc + STAGES - 1) % STAGES, kc + STAGES - 1);
            cp_commit();
        }

        // --- ks=0 MMAs on preloaded fragments ---
        #pragma unroll
        for (int mi = 0; mi < 4; mi++)
            #pragma unroll
            for (int ni = 0; ni < 8; ni++)
                mma_f16(acc[mi][ni], af0[mi], bf0[ni]);

        // --- ks = 1..3 ---
        #pragma unroll
        for (int ks = 1; ks < 4; ks++) {
            const unsigned cb = (unsigned)ks * 32u;
            uint32_t af[4][4];
            #pragma unroll
            for (int mi = 0; mi < 4; mi++)
                ldsm_x4(sa + swz(aRow + mi * 16u, cb + aColHalf),
                        af[mi][0], af[mi][1], af[mi][2], af[mi][3]);
            uint32_t bf[8][2];
            #pragma unroll
            for (int p = 0; p < 4; p++)
                ldsm_x4(sb + swz(bRow + p * 16u, cb + bColHalf),
                        bf[2*p][0], bf[2*p][1], bf[2*p+1][0], bf[2*p+1][1]);
            #pragma unroll
            for (int mi = 0; mi < 4; mi++)
                #pragma unroll
                for (int ni = 0; ni < 8; ni++)
                    mma_f16(acc[mi][ni], af[mi], bf[ni]);
        }
    }

    const float sx = 448.f / (g_scales[0] + 1e-6f);
    const float sw = 448.f / (g_scales[1] + 1e-6f);
    const float inv = 1.0f / (sx * sw);

    #pragma unroll
    for (int mi = 0; mi < 4; mi++) {
        const unsigned r0 = mBase + warpM * 64 + mi * 16 + lr;
        #pragma unroll
        for (int ni = 0; ni < 8; ni++) {
            const unsigned c = nBase + warpN * 64 + ni * 8 + lc * 2;
            const float2 bv = *(const float2*)(bias + c);
            const float* a = acc[mi][ni];
            uint16_t p0 = cvt2_e4m3(fmaf(a[0], inv, bv.x), fmaf(a[1], inv, bv.y));
            uint16_t p1 = cvt2_e4m3(fmaf(a[2], inv, bv.x), fmaf(a[3], inv, bv.y));
            float2 f0 = dec2_e4m3(p0);
            float2 f1 = dec2_e4m3(p1);
            *(float2*)(out + (size_t)r0       * NOUT + c) = f0;
            *(float2*)(out + (size_t)(r0 + 8) * NOUT + c) = f1;
        }
    }

    // Re-zero absmax accumulators for next replay (no reader in this kernel).
    if (tid < 2) g_absmax_bits[tid] = 0u;
}

// ---------------------------------------------------------------------------
extern "C" void kernel_launch(void* const* d_in, const int* in_sizes, int n_in,
                              void* d_out, int out_size)
{
    const float* x = (const float*)d_in[0];
    const float* w = (const float*)d_in[1];
    const float* b = (const float*)d_in[2];
    float* out = (float*)d_out;

    absmax_fused_kernel<<<AX_XBLK + AX_WBLK, 256>>>((const float4*)x,
                                                    (const float4*)w);   // #1
    quant_fused_kernel<<<QT_XBLK + QT_WBLK, 256>>>((const float4*)x,
                                                   (const float4*)w);    // #2

    cudaFuncSetAttribute(gemm_kernel, cudaFuncAttributeMaxDynamicSharedMemorySize, SMEM_TOTAL);
    dim3 grid(TOKENS / TM, NOUT / TN);   // (32, 128)
    gemm_kernel<<<grid, NTHREADS, SMEM_TOTAL>>>(b, out);                 // #3

    (void)in_sizes; (void)n_in; (void)out_size;
}